// round 15
// baseline (speedup 1.0000x reference)
#include <cuda_runtime.h>
#include <cuda_bf16.h>
#include <cstdint>

// ---------------------------------------------------------------------------
// TRIZRL: encoder(tanh) -> 40-expert batched GEMM(+bias,relu) -> softmax router
//         -> jax.random.categorical(threefry, partitionable) -> gather -> decoder
// Outputs: out[B,5], probs[B,40], h[B,40,64]
// R15: h-GEMM via int8 IMMA m16n8k32, 2-limb fixed-point split:
//      z ~ (a1 + a2/128)/127, w ~ (b1 + b2/128)*WMAX/127
//      h = C*(G1 + G2/128),  G1 = a1.b1 (K=64), G2 = [a1|a2].[b2|b1] (K=128)
// ---------------------------------------------------------------------------

#define MAXB 131072
#define NEXP 40
#define HID  64
#define NCOL (NEXP * HID)   // 2560
#define KB8  192            // int8 concat K bytes per row
#define SPAD8 208           // smem row stride in bytes (conflict-free, 16B aligned)
#define WMAX 0.8f

__device__ float  g_z  [(size_t)MAXB * HID];
__device__ int8_t g_zc8[(size_t)MAXB * KB8];   // A: [a1 | a1 | a2]
__device__ int8_t g_wc8[(size_t)NCOL * KB8];   // B: [b1 | b2 | b1]
__device__ int    g_idx[MAXB];

// ---------------- Threefry-2x32-20, key (0,1); partitionable path ----------
__device__ __forceinline__ uint2 threefry01(uint32_t x0, uint32_t x1) {
    const uint32_t ks0 = 0u, ks1 = 1u, ks2 = 0x1BD11BDBu;
    x0 += ks0; x1 += ks1;
#define TFR(r) { x0 += x1; x1 = (x1 << (r)) | (x1 >> (32 - (r))); x1 ^= x0; }
    TFR(13) TFR(15) TFR(26) TFR(6)   x0 += ks1; x1 += ks2 + 1u;
    TFR(17) TFR(29) TFR(16) TFR(24)  x0 += ks2; x1 += ks0 + 2u;
    TFR(13) TFR(15) TFR(26) TFR(6)   x0 += ks0; x1 += ks1 + 3u;
    TFR(17) TFR(29) TFR(16) TFR(24)  x0 += ks1; x1 += ks2 + 4u;
    TFR(13) TFR(15) TFR(26) TFR(6)   x0 += ks2; x1 += ks0 + 5u;
#undef TFR
    return make_uint2(x0, x1);
}
__device__ __forceinline__ float gumbel_sample(uint32_t flat_idx) {
    uint2 r = threefry01(0u, flat_idx);
    uint32_t bits = r.x ^ r.y;
    float f = __uint_as_float((bits >> 9) | 0x3f800000u) - 1.0f;
    float u = fmaxf(f, 1.17549435e-38f);
    return -logf(-logf(u));
}

__device__ __forceinline__ int8_t q8(float v) {
    int i = __float2int_rn(v);
    i = max(-127, min(127, i));
    return (int8_t)i;
}

// ---------------- Kernel 1: encoder (+ int8 limb emit) ---------------------
__global__ void enc_kernel(const float* __restrict__ x,
                           const float* __restrict__ ew,
                           const float* __restrict__ eb) {
    int t = blockIdx.x * blockDim.x + threadIdx.x;
    int b = t >> 6, j = t & 63;
    const float* xr = x + (size_t)b * 5;
    float a = __ldg(eb + j);
    #pragma unroll
    for (int d = 0; d < 5; ++d) a = fmaf(__ldg(xr + d), __ldg(ew + j * 5 + d), a);
    float z = tanhf(a);
    g_z[t] = z;
    float zs = z * 127.0f;
    int a1 = __float2int_rn(zs);
    a1 = max(-127, min(127, a1));
    float r = zs - (float)a1;
    int8_t a2 = q8(r * 128.0f);
    int8_t* row = g_zc8 + (size_t)b * KB8;
    row[j]       = (int8_t)a1;
    row[j + 64]  = (int8_t)a1;
    row[j + 128] = a2;
}

// ---------------- Kernel 1b: weight int8 limb split ------------------------
__global__ void wsplit_kernel(const float* __restrict__ w) {
    int i = blockIdx.x * 256 + threadIdx.x;
    if (i >= NCOL * HID) return;
    int n = i >> 6, k = i & 63;
    float ws = w[i] * (127.0f / WMAX);
    int b1 = __float2int_rn(ws);
    b1 = max(-127, min(127, b1));
    float r = ws - (float)b1;
    int8_t b2 = q8(r * 128.0f);
    int8_t* row = g_wc8 + (size_t)n * KB8;
    row[k]       = (int8_t)b1;
    row[k + 64]  = b2;
    row[k + 128] = (int8_t)b1;
}

// ---------------- Kernel 2: router softmax + categorical -------------------
__global__ void policy_kernel(const float* __restrict__ pol_w,
                              const float* __restrict__ pol_b,
                              float* __restrict__ probs, int B) {
    __shared__ float sW[NEXP * 65];
    __shared__ float sB[NEXP];
    __shared__ float sZ[8][HID];
    int tid = threadIdx.x;
    for (int i = tid; i < NEXP * HID; i += 256)
        sW[(i / HID) * 65 + (i % HID)] = pol_w[i];
    if (tid < NEXP) sB[tid] = pol_b[tid];
    __syncthreads();

    int wid = tid >> 5, lane = tid & 31;
    int gw = blockIdx.x * 8 + wid;
    int warpsTotal = gridDim.x * 8;

    for (int b = gw; b < B; b += warpsTotal) {
        const float* zr = g_z + (size_t)b * HID;
        sZ[wid][lane]      = zr[lane];
        sZ[wid][lane + 32] = zr[lane + 32];
        __syncwarp();

        float acc1 = 0.f, acc2 = 0.f;
        #pragma unroll
        for (int d = 0; d < HID; ++d) {
            float zd = sZ[wid][d];
            acc1 = fmaf(zd, sW[lane * 65 + d], acc1);
            if (lane < 8) acc2 = fmaf(zd, sW[(lane + 32) * 65 + d], acc2);
        }
        float v1 = acc1 + sB[lane];
        float v2 = (lane < 8) ? (acc2 + sB[lane + 32]) : -INFINITY;

        float m = fmaxf(v1, v2);
        #pragma unroll
        for (int off = 16; off; off >>= 1) m = fmaxf(m, __shfl_xor_sync(~0u, m, off));
        float e1 = expf(v1 - m);
        float e2 = (lane < 8) ? expf(v2 - m) : 0.f;
        float s = e1 + e2;
        #pragma unroll
        for (int off = 16; off; off >>= 1) s += __shfl_xor_sync(~0u, s, off);
        float p1 = e1 / s, p2 = e2 / s;
        probs[(size_t)b * NEXP + lane] = p1;
        if (lane < 8) probs[(size_t)b * NEXP + 32 + lane] = p2;

        uint32_t base = (uint32_t)b * (uint32_t)NEXP;
        float val1 = logf(p1) + gumbel_sample(base + lane);
        float val2 = -INFINITY;
        if (lane < 8) val2 = logf(p2) + gumbel_sample(base + 32 + lane);

        float bv; int bk;
        if (val2 > val1) { bv = val2; bk = lane + 32; } else { bv = val1; bk = lane; }
        #pragma unroll
        for (int off = 16; off; off >>= 1) {
            float ov = __shfl_xor_sync(~0u, bv, off);
            int   ok = __shfl_xor_sync(~0u, bk, off);
            if (ov > bv || (ov == bv && ok < bk)) { bv = ov; bk = ok; }
        }
        if (lane == 0) g_idx[b] = bk;
        __syncwarp();
    }
}

// ---------------- Kernel 3: h-GEMM, int8 IMMA m16n8k32 ---------------------
__device__ __forceinline__ uint32_t smem_u32(const void* p) {
    uint32_t a;
    asm("{ .reg .u64 t; cvta.to.shared.u64 t, %1; cvt.u32.u64 %0, t; }" : "=r"(a) : "l"(p));
    return a;
}
#define LDMX4(r0, r1, r2, r3, addr) \
    asm volatile("ldmatrix.sync.aligned.m8n8.x4.shared.b16 {%0,%1,%2,%3}, [%4];" \
        : "=r"(r0), "=r"(r1), "=r"(r2), "=r"(r3) : "r"(addr))
#define IMMA(acc, a, b) \
    asm volatile( \
        "mma.sync.aligned.m16n8k32.row.col.s32.s8.s8.s32 " \
        "{%0,%1,%2,%3}, {%4,%5,%6,%7}, {%8,%9}, {%0,%1,%2,%3};" \
        : "+r"((acc)[0]), "+r"((acc)[1]), "+r"((acc)[2]), "+r"((acc)[3]) \
        : "r"((a)[0]), "r"((a)[1]), "r"((a)[2]), "r"((a)[3]), \
          "r"((b)[0]), "r"((b)[1]))

// 4x4 transpose of float2 elements within a quad (2 shfl_xor stages).
__device__ __forceinline__ void quad_tr4(unsigned long long* P, int lc) {
    {
        bool hi = lc & 2;
        unsigned long long s0 = hi ? P[0] : P[2];
        unsigned long long s1 = hi ? P[1] : P[3];
        unsigned long long r0 = __shfl_xor_sync(0xffffffffu, s0, 2);
        unsigned long long r1 = __shfl_xor_sync(0xffffffffu, s1, 2);
        if (hi) { P[0] = r0; P[1] = r1; } else { P[2] = r0; P[3] = r1; }
    }
    {
        bool od = lc & 1;
        unsigned long long s0 = od ? P[0] : P[1];
        unsigned long long s1 = od ? P[2] : P[3];
        unsigned long long r0 = __shfl_xor_sync(0xffffffffu, s0, 1);
        unsigned long long r1 = __shfl_xor_sync(0xffffffffu, s1, 1);
        if (od) { P[0] = r0; P[2] = r1; } else { P[1] = r0; P[3] = r1; }
    }
}
__device__ __forceinline__ unsigned long long pack2(float x, float y) {
    unsigned long long r;
    asm("mov.b64 %0, {%1, %2};" : "=l"(r) : "f"(x), "f"(y));
    return r;
}
__device__ __forceinline__ float2 unpack2(unsigned long long v) {
    float2 r;
    asm("mov.b64 {%0, %1}, %2;" : "=f"(r.x), "=f"(r.y) : "l"(v));
    return r;
}

// CTA: M=128 rows resident (A smem 128 x 192B). 40 N-tiles of 64.
// 8 warps 4m x 2n, warp tile m32 x n32. Two s32 acc groups (G1 K=64, G2 K=128).
__global__ void __launch_bounds__(256, 2)
gemm_h_mma(const float* __restrict__ bias, float* __restrict__ H) {
    __shared__ int8_t As[128 * SPAD8];
    __shared__ int8_t Bs[64 * SPAD8];

    int tid = threadIdx.x;
    size_t bm = (size_t)blockIdx.x * 128;

    // A tile: 128 rows x 192 B = 1536 x 16B chunks (once per CTA)
    #pragma unroll
    for (int it = 0; it < 6; ++it) {
        int i = tid + it * 256;
        int m = i / 12, c = i % 12;
        uint4 v = *(const uint4*)(g_zc8 + (bm + m) * KB8 + c * 16);
        *(uint4*)(As + m * SPAD8 + c * 16) = v;
    }

    int wid = tid >> 5, lane = tid & 31;
    int mw = (wid & 3) * 32;        // warp m offset
    int nw = (wid >> 2) * 32;       // warp n offset
    int lr = lane >> 2, lc = lane & 3;

    uint32_t sbA = smem_u32(As), sbB = smem_u32(Bs);
    uint32_t aoff = sbA + ((lane & 7) + ((lane >> 3) & 1) * 8) * SPAD8
                        + ((lane >> 4) & 1) * 16;
    uint32_t boff = sbB + (size_t)0 + nw * SPAD8
                        + ((lane & 7) + ((lane >> 4) & 1) * 8) * SPAD8
                        + ((lane >> 3) & 1) * 16;

    const float C1 = WMAX / (127.0f * 127.0f);
    const float C2 = C1 * 0.0078125f;   // /128

    for (int t = 0; t < NEXP; ++t) {
        int bn = t * 64;
        __syncthreads();                   // Bs consumed
        // B tile: 64 rows x 192 B = 768 chunks
        #pragma unroll
        for (int it = 0; it < 3; ++it) {
            int i = tid + it * 256;
            int n = i / 12, c = i % 12;
            uint4 v = *(const uint4*)(g_wc8 + (size_t)(bn + n) * KB8 + c * 16);
            *(uint4*)(Bs + n * SPAD8 + c * 16) = v;
        }
        __syncthreads();                   // Bs ready

        int acc1[2][4][4], acc2[2][4][4];
        #pragma unroll
        for (int f = 0; f < 2; ++f)
            #pragma unroll
            for (int g = 0; g < 4; ++g)
                #pragma unroll
                for (int e = 0; e < 4; ++e) { acc1[f][g][e] = 0; acc2[f][g][e] = 0; }

        #pragma unroll
        for (int ks = 0; ks < 6; ++ks) {   // ks 0-1: G1 (K=64); ks 2-5: G2 (K=128)
            uint32_t a[2][4], b[4][2];
            #pragma unroll
            for (int f = 0; f < 2; ++f)
                LDMX4(a[f][0], a[f][1], a[f][2], a[f][3],
                      aoff + (mw + f * 16) * SPAD8 + ks * 32);
            #pragma unroll
            for (int gp = 0; gp < 2; ++gp)
                LDMX4(b[gp * 2][0], b[gp * 2][1], b[gp * 2 + 1][0], b[gp * 2 + 1][1],
                      boff + ks * 32 + gp * (16 * SPAD8));
            #pragma unroll
            for (int f = 0; f < 2; ++f)
                #pragma unroll
                for (int g = 0; g < 4; ++g) {
                    if (ks < 2) IMMA(acc1[f][g], a[f], b[g]);
                    else        IMMA(acc2[f][g], a[f], b[g]);
                }
        }

        // Epilogue: combine limb groups, bias+relu, quad transpose, STG.128.
        #pragma unroll
        for (int f = 0; f < 2; ++f) {
            unsigned long long P[4], Q[4];
            #pragma unroll
            for (int g = 0; g < 4; ++g) {
                int col = bn + nw + g * 8 + lc * 2;
                float b0 = __ldg(bias + col), b1 = __ldg(bias + col + 1);
                float v0 = fmaf((float)acc1[f][g][0], C1,
                                fmaf((float)acc2[f][g][0], C2, b0));
                float v1 = fmaf((float)acc1[f][g][1], C1,
                                fmaf((float)acc2[f][g][1], C2, b1));
                float v2 = fmaf((float)acc1[f][g][2], C1,
                                fmaf((float)acc2[f][g][2], C2, b0));
                float v3 = fmaf((float)acc1[f][g][3], C1,
                                fmaf((float)acc2[f][g][3], C2, b1));
                P[g] = pack2(fmaxf(v0, 0.f), fmaxf(v1, 0.f));
                Q[g] = pack2(fmaxf(v2, 0.f), fmaxf(v3, 0.f));
            }
            quad_tr4(P, lc);
            quad_tr4(Q, lc);
            size_t r0 = bm + mw + f * 16 + lr;
            float* o0 = H + r0 * NCOL + bn + nw + lc * 8;
            float* o1 = o0 + (size_t)8 * NCOL;
            float2 p0 = unpack2(P[0]), p1 = unpack2(P[1]);
            float2 p2 = unpack2(P[2]), p3 = unpack2(P[3]);
            float2 q0 = unpack2(Q[0]), q1 = unpack2(Q[1]);
            float2 q2 = unpack2(Q[2]), q3 = unpack2(Q[3]);
            *(float4*)(o0)     = make_float4(p0.x, p0.y, p1.x, p1.y);
            *(float4*)(o0 + 4) = make_float4(p2.x, p2.y, p3.x, p3.y);
            *(float4*)(o1)     = make_float4(q0.x, q0.y, q1.x, q1.y);
            *(float4*)(o1 + 4) = make_float4(q2.x, q2.y, q3.x, q3.y);
        }
    }
}

// ---------------- Kernel 4: decoder ----------------------------------------
__global__ void dec_kernel(const float* __restrict__ H,
                           const float* __restrict__ dw,
                           const float* __restrict__ db,
                           float* __restrict__ out, int B) {
    __shared__ float sw[5 * HID];
    __shared__ float sb[5];
    int tid = threadIdx.x;
    for (int i = tid; i < 5 * HID; i += 256) sw[i] = dw[i];
    if (tid < 5) sb[tid] = db[tid];
    __syncthreads();

    int b = blockIdx.x * 256 + tid;
    if (b >= B) return;
    const float4* hr = (const float4*)(H + (size_t)b * NCOL + g_idx[b] * HID);
    float acc[5];
    #pragma unroll
    for (int j = 0; j < 5; ++j) acc[j] = sb[j];
    #pragma unroll
    for (int q = 0; q < 16; ++q) {
        float4 v = hr[q];
        #pragma unroll
        for (int j = 0; j < 5; ++j) {
            acc[j] = fmaf(v.x, sw[j * HID + q * 4 + 0], acc[j]);
            acc[j] = fmaf(v.y, sw[j * HID + q * 4 + 1], acc[j]);
            acc[j] = fmaf(v.z, sw[j * HID + q * 4 + 2], acc[j]);
            acc[j] = fmaf(v.w, sw[j * HID + q * 4 + 3], acc[j]);
        }
    }
    float* o = out + (size_t)b * 5;
    #pragma unroll
    for (int j = 0; j < 5; ++j) o[j] = acc[j];
}

// ---------------------------------------------------------------------------
extern "C" void kernel_launch(void* const* d_in, const int* in_sizes, int n_in,
                              void* d_out, int out_size) {
    const float* x      = (const float*)d_in[0];
    const float* enc_w  = (const float*)d_in[1];
    const float* enc_b  = (const float*)d_in[2];
    const float* triz_w = (const float*)d_in[3];   // [40,64,64] == W[2560,64]
    const float* triz_b = (const float*)d_in[4];   // [40,64]    == bias[2560]
    const float* pol_w  = (const float*)d_in[5];
    const float* pol_b  = (const float*)d_in[6];
    const float* dec_w  = (const float*)d_in[7];
    const float* dec_b  = (const float*)d_in[8];

    int B = in_sizes[0] / 5;

    float* out   = (float*)d_out;                  // [B,5]
    float* probs = out + (size_t)B * 5;            // [B,40]
    float* h     = probs + (size_t)B * NEXP;       // [B,40,64]

    enc_kernel<<<(B * HID) / 256, 256>>>(x, enc_w, enc_b);
    wsplit_kernel<<<(NCOL * HID + 255) / 256, 256>>>(triz_w);
    policy_kernel<<<1024, 256>>>(pol_w, pol_b, probs, B);

    gemm_h_mma<<<B / 128, 256>>>(triz_b, h);

    dec_kernel<<<(B + 255) / 256, 256>>>(h, dec_w, dec_b, out, B);
}

// round 16
// speedup vs baseline: 1.1673x; 1.1673x over previous
#include <cuda_runtime.h>
#include <cuda_bf16.h>
#include <cstdint>

// ---------------------------------------------------------------------------
// TRIZRL: encoder(tanh) -> 40-expert batched GEMM(+bias,relu) -> softmax router
//         -> jax.random.categorical(threefry, partitionable) -> gather -> decoder
// Outputs: out[B,5], probs[B,40], h[B,40,64]
// R16: bf16 HMMA split-GEMM with DE-DUPLICATED limbs: A=[z1|z2], B=[w1|w2],
//      3 terms via smem offsets. 52.2KB smem/CTA -> 3 CTAs/SM (24 warps).
// ---------------------------------------------------------------------------

#define MAXB 131072
#define NEXP 40
#define HID  64
#define NCOL (NEXP * HID)   // 2560
#define KL   128            // limb-concat K (z1|z2), bf16
#define SPAD 136            // smem row stride in bf16 (272B, ldmatrix conflict-free)
#define ROWB 272

__device__ float         g_z [(size_t)MAXB * HID];
__device__ __nv_bfloat16 g_zc[(size_t)MAXB * KL];   // [z1 | z2]
__device__ __nv_bfloat16 g_wc[(size_t)NCOL * KL];   // [w1 | w2]
__device__ int           g_idx[MAXB];

// ---------------- Threefry-2x32-20, key (0,1); partitionable path ----------
__device__ __forceinline__ uint2 threefry01(uint32_t x0, uint32_t x1) {
    const uint32_t ks0 = 0u, ks1 = 1u, ks2 = 0x1BD11BDBu;
    x0 += ks0; x1 += ks1;
#define TFR(r) { x0 += x1; x1 = (x1 << (r)) | (x1 >> (32 - (r))); x1 ^= x0; }
    TFR(13) TFR(15) TFR(26) TFR(6)   x0 += ks1; x1 += ks2 + 1u;
    TFR(17) TFR(29) TFR(16) TFR(24)  x0 += ks2; x1 += ks0 + 2u;
    TFR(13) TFR(15) TFR(26) TFR(6)   x0 += ks0; x1 += ks1 + 3u;
    TFR(17) TFR(29) TFR(16) TFR(24)  x0 += ks1; x1 += ks2 + 4u;
    TFR(13) TFR(15) TFR(26) TFR(6)   x0 += ks2; x1 += ks0 + 5u;
#undef TFR
    return make_uint2(x0, x1);
}
__device__ __forceinline__ float gumbel_sample(uint32_t flat_idx) {
    uint2 r = threefry01(0u, flat_idx);
    uint32_t bits = r.x ^ r.y;
    float f = __uint_as_float((bits >> 9) | 0x3f800000u) - 1.0f;
    float u = fmaxf(f, 1.17549435e-38f);
    return -logf(-logf(u));
}

// ---------------- Kernel 1: encoder (+ limb emit) --------------------------
__global__ void enc_kernel(const float* __restrict__ x,
                           const float* __restrict__ ew,
                           const float* __restrict__ eb) {
    int t = blockIdx.x * blockDim.x + threadIdx.x;
    int b = t >> 6, j = t & 63;
    const float* xr = x + (size_t)b * 5;
    float a = __ldg(eb + j);
    #pragma unroll
    for (int d = 0; d < 5; ++d) a = fmaf(__ldg(xr + d), __ldg(ew + j * 5 + d), a);
    float z = tanhf(a);
    g_z[t] = z;
    __nv_bfloat16 hi = __float2bfloat16(z);
    __nv_bfloat16 lo = __float2bfloat16(z - __bfloat162float(hi));
    __nv_bfloat16* row = g_zc + (size_t)b * KL;
    row[j]      = hi;
    row[j + 64] = lo;
}

// ---------------- Kernel 1b: weight limb split -----------------------------
__global__ void wsplit_kernel(const float* __restrict__ w) {
    int i = blockIdx.x * 256 + threadIdx.x;
    if (i >= NCOL * HID) return;
    int n = i >> 6, k = i & 63;
    float v = w[i];
    __nv_bfloat16 hi = __float2bfloat16(v);
    __nv_bfloat16 lo = __float2bfloat16(v - __bfloat162float(hi));
    __nv_bfloat16* row = g_wc + (size_t)n * KL;
    row[k]      = hi;
    row[k + 64] = lo;
}

// ---------------- Kernel 2: router softmax + categorical (FROZEN) ----------
__global__ void policy_kernel(const float* __restrict__ pol_w,
                              const float* __restrict__ pol_b,
                              float* __restrict__ probs, int B) {
    __shared__ float sW[NEXP * 65];
    __shared__ float sB[NEXP];
    __shared__ float sZ[8][HID];
    int tid = threadIdx.x;
    for (int i = tid; i < NEXP * HID; i += 256)
        sW[(i / HID) * 65 + (i % HID)] = pol_w[i];
    if (tid < NEXP) sB[tid] = pol_b[tid];
    __syncthreads();

    int wid = tid >> 5, lane = tid & 31;
    int gw = blockIdx.x * 8 + wid;
    int warpsTotal = gridDim.x * 8;

    for (int b = gw; b < B; b += warpsTotal) {
        const float* zr = g_z + (size_t)b * HID;
        sZ[wid][lane]      = zr[lane];
        sZ[wid][lane + 32] = zr[lane + 32];
        __syncwarp();

        float acc1 = 0.f, acc2 = 0.f;
        #pragma unroll
        for (int d = 0; d < HID; ++d) {
            float zd = sZ[wid][d];
            acc1 = fmaf(zd, sW[lane * 65 + d], acc1);
            if (lane < 8) acc2 = fmaf(zd, sW[(lane + 32) * 65 + d], acc2);
        }
        float v1 = acc1 + sB[lane];
        float v2 = (lane < 8) ? (acc2 + sB[lane + 32]) : -INFINITY;

        float m = fmaxf(v1, v2);
        #pragma unroll
        for (int off = 16; off; off >>= 1) m = fmaxf(m, __shfl_xor_sync(~0u, m, off));
        float e1 = expf(v1 - m);
        float e2 = (lane < 8) ? expf(v2 - m) : 0.f;
        float s = e1 + e2;
        #pragma unroll
        for (int off = 16; off; off >>= 1) s += __shfl_xor_sync(~0u, s, off);
        float p1 = e1 / s, p2 = e2 / s;
        probs[(size_t)b * NEXP + lane] = p1;
        if (lane < 8) probs[(size_t)b * NEXP + 32 + lane] = p2;

        uint32_t base = (uint32_t)b * (uint32_t)NEXP;
        float val1 = logf(p1) + gumbel_sample(base + lane);
        float val2 = -INFINITY;
        if (lane < 8) val2 = logf(p2) + gumbel_sample(base + 32 + lane);

        float bv; int bk;
        if (val2 > val1) { bv = val2; bk = lane + 32; } else { bv = val1; bk = lane; }
        #pragma unroll
        for (int off = 16; off; off >>= 1) {
            float ov = __shfl_xor_sync(~0u, bv, off);
            int   ok = __shfl_xor_sync(~0u, bk, off);
            if (ov > bv || (ov == bv && ok < bk)) { bv = ov; bk = ok; }
        }
        if (lane == 0) g_idx[b] = bk;
        __syncwarp();
    }
}

// ---------------- Kernel 3: h-GEMM, ldmatrix + mma.sync bf16 ----------------
__device__ __forceinline__ uint32_t smem_u32(const void* p) {
    uint32_t a;
    asm("{ .reg .u64 t; cvta.to.shared.u64 t, %1; cvt.u32.u64 %0, t; }" : "=r"(a) : "l"(p));
    return a;
}
#define LDMX4(r0, r1, r2, r3, addr) \
    asm volatile("ldmatrix.sync.aligned.m8n8.x4.shared.b16 {%0,%1,%2,%3}, [%4];" \
        : "=r"(r0), "=r"(r1), "=r"(r2), "=r"(r3) : "r"(addr))

// 4x4 transpose of float2 elements within a quad (2 shfl_xor stages).
__device__ __forceinline__ void quad_tr4(unsigned long long* P, int lc) {
    {
        bool hi = lc & 2;
        unsigned long long s0 = hi ? P[0] : P[2];
        unsigned long long s1 = hi ? P[1] : P[3];
        unsigned long long r0 = __shfl_xor_sync(0xffffffffu, s0, 2);
        unsigned long long r1 = __shfl_xor_sync(0xffffffffu, s1, 2);
        if (hi) { P[0] = r0; P[1] = r1; } else { P[2] = r0; P[3] = r1; }
    }
    {
        bool od = lc & 1;
        unsigned long long s0 = od ? P[0] : P[1];
        unsigned long long s1 = od ? P[2] : P[3];
        unsigned long long r0 = __shfl_xor_sync(0xffffffffu, s0, 1);
        unsigned long long r1 = __shfl_xor_sync(0xffffffffu, s1, 1);
        if (od) { P[0] = r0; P[2] = r1; } else { P[1] = r0; P[3] = r1; }
    }
}
__device__ __forceinline__ unsigned long long pack2(float x, float y) {
    unsigned long long r;
    asm("mov.b64 %0, {%1, %2};" : "=l"(r) : "f"(x), "f"(y));
    return r;
}
__device__ __forceinline__ float2 unpack2(unsigned long long v) {
    float2 r;
    asm("mov.b64 {%0, %1}, %2;" : "=f"(r.x), "=f"(r.y) : "l"(v));
    return r;
}

// CTA: M=128 rows resident (A smem 128x272B = [z1|z2]). 40 N-tiles of 64.
// 8 warps 4m x 2n, warp tile m32 x n32. 3 split terms via smem byte offsets:
//   (z1,w1): A+0,  B+0    (z1,w2): A+0,  B+128   (z2,w1): A+128, B+0
__global__ void __launch_bounds__(256, 3)
gemm_h_mma(const float* __restrict__ bias, float* __restrict__ H) {
    extern __shared__ __nv_bfloat16 sm[];
    __nv_bfloat16* As = sm;               // [128][SPAD]
    __nv_bfloat16* Bs = sm + 128 * SPAD;  // [64][SPAD]

    int tid = threadIdx.x;
    size_t bm = (size_t)blockIdx.x * 128;

    // A tile: 128 rows x 256B = 2048 x 16B chunks
    #pragma unroll
    for (int it = 0; it < 8; ++it) {
        int i = tid + it * 256;
        int m = i >> 4, c = i & 15;
        uint4 v = *(const uint4*)(g_zc + (bm + m) * KL + c * 8);
        *(uint4*)(As + m * SPAD + c * 8) = v;
    }

    int wid = tid >> 5, lane = tid & 31;
    int mw = (wid & 3) * 32;        // warp m offset
    int nw = (wid >> 2) * 32;       // warp n offset
    int lr = lane >> 2, lc = lane & 3;

    uint32_t sbA = smem_u32(As), sbB = smem_u32(Bs);
    uint32_t aoff = sbA + (((lane & 7) + ((lane >> 3) & 1) * 8) * ROWB
                           + ((lane >> 4) & 1) * 16);
    uint32_t boff = sbB + nw * ROWB + (((lane & 7) + ((lane >> 4) & 1) * 8) * ROWB
                           + ((lane >> 3) & 1) * 16);

    // term smem byte offsets within a row: {A, B}
    const int ta[3] = {0, 0, 128};
    const int tb[3] = {0, 128, 0};

    for (int t = 0; t < NEXP; ++t) {
        int bn = t * 64;
        __syncthreads();                   // Bs consumed
        // B tile: 64 rows x 256B = 1024 chunks
        #pragma unroll
        for (int it = 0; it < 4; ++it) {
            int i = tid + it * 256;
            int n = i >> 4, c = i & 15;
            uint4 v = *(const uint4*)(g_wc + (size_t)(bn + n) * KL + c * 8);
            *(uint4*)(Bs + n * SPAD + c * 8) = v;
        }
        __syncthreads();                   // Bs ready

        float acc[2][4][4];
        #pragma unroll
        for (int f = 0; f < 2; ++f)
            #pragma unroll
            for (int g = 0; g < 4; ++g)
                #pragma unroll
                for (int e = 0; e < 4; ++e) acc[f][g][e] = 0.f;

        #pragma unroll
        for (int term = 0; term < 3; ++term) {
            #pragma unroll
            for (int s = 0; s < 4; ++s) {     // 4 k16-steps per 64-wide limb
                uint32_t a[2][4], b[4][2];
                #pragma unroll
                for (int f = 0; f < 2; ++f)
                    LDMX4(a[f][0], a[f][1], a[f][2], a[f][3],
                          aoff + (mw + f * 16) * ROWB + ta[term] + s * 32);
                LDMX4(b[0][0], b[0][1], b[1][0], b[1][1],
                      boff + tb[term] + s * 32);
                LDMX4(b[2][0], b[2][1], b[3][0], b[3][1],
                      boff + tb[term] + s * 32 + 16 * ROWB);
                #pragma unroll
                for (int f = 0; f < 2; ++f)
                    #pragma unroll
                    for (int g = 0; g < 4; ++g)
                        asm volatile(
                            "mma.sync.aligned.m16n8k16.row.col.f32.bf16.bf16.f32 "
                            "{%0,%1,%2,%3}, {%4,%5,%6,%7}, {%8,%9}, {%0,%1,%2,%3};"
                            : "+f"(acc[f][g][0]), "+f"(acc[f][g][1]),
                              "+f"(acc[f][g][2]), "+f"(acc[f][g][3])
                            : "r"(a[f][0]), "r"(a[f][1]), "r"(a[f][2]), "r"(a[f][3]),
                              "r"(b[g][0]), "r"(b[g][1]));
            }
        }

        // Epilogue: bias+relu, quad transpose, STG.128.
        #pragma unroll
        for (int f = 0; f < 2; ++f) {
            unsigned long long P[4], Q[4];
            #pragma unroll
            for (int g = 0; g < 4; ++g) {
                int col = bn + nw + g * 8 + lc * 2;
                float b0 = __ldg(bias + col), b1 = __ldg(bias + col + 1);
                P[g] = pack2(fmaxf(acc[f][g][0] + b0, 0.f),
                             fmaxf(acc[f][g][1] + b1, 0.f));
                Q[g] = pack2(fmaxf(acc[f][g][2] + b0, 0.f),
                             fmaxf(acc[f][g][3] + b1, 0.f));
            }
            quad_tr4(P, lc);
            quad_tr4(Q, lc);
            size_t r0 = bm + mw + f * 16 + lr;
            float* o0 = H + r0 * NCOL + bn + nw + lc * 8;
            float* o1 = o0 + (size_t)8 * NCOL;
            float2 p0 = unpack2(P[0]), p1 = unpack2(P[1]);
            float2 p2 = unpack2(P[2]), p3 = unpack2(P[3]);
            float2 q0 = unpack2(Q[0]), q1 = unpack2(Q[1]);
            float2 q2 = unpack2(Q[2]), q3 = unpack2(Q[3]);
            *(float4*)(o0)     = make_float4(p0.x, p0.y, p1.x, p1.y);
            *(float4*)(o0 + 4) = make_float4(p2.x, p2.y, p3.x, p3.y);
            *(float4*)(o1)     = make_float4(q0.x, q0.y, q1.x, q1.y);
            *(float4*)(o1 + 4) = make_float4(q2.x, q2.y, q3.x, q3.y);
        }
    }
}

// ---------------- Kernel 4: decoder ----------------------------------------
__global__ void dec_kernel(const float* __restrict__ H,
                           const float* __restrict__ dw,
                           const float* __restrict__ db,
                           float* __restrict__ out, int B) {
    __shared__ float sw[5 * HID];
    __shared__ float sb[5];
    int tid = threadIdx.x;
    for (int i = tid; i < 5 * HID; i += 256) sw[i] = dw[i];
    if (tid < 5) sb[tid] = db[tid];
    __syncthreads();

    int b = blockIdx.x * 256 + tid;
    if (b >= B) return;
    const float4* hr = (const float4*)(H + (size_t)b * NCOL + g_idx[b] * HID);
    float acc[5];
    #pragma unroll
    for (int j = 0; j < 5; ++j) acc[j] = sb[j];
    #pragma unroll
    for (int q = 0; q < 16; ++q) {
        float4 v = hr[q];
        #pragma unroll
        for (int j = 0; j < 5; ++j) {
            acc[j] = fmaf(v.x, sw[j * HID + q * 4 + 0], acc[j]);
            acc[j] = fmaf(v.y, sw[j * HID + q * 4 + 1], acc[j]);
            acc[j] = fmaf(v.z, sw[j * HID + q * 4 + 2], acc[j]);
            acc[j] = fmaf(v.w, sw[j * HID + q * 4 + 3], acc[j]);
        }
    }
    float* o = out + (size_t)b * 5;
    #pragma unroll
    for (int j = 0; j < 5; ++j) o[j] = acc[j];
}

// ---------------------------------------------------------------------------
#define SMEM_MMA ((128 * SPAD + 64 * SPAD) * 2)   // 52224 bytes

extern "C" void kernel_launch(void* const* d_in, const int* in_sizes, int n_in,
                              void* d_out, int out_size) {
    const float* x      = (const float*)d_in[0];
    const float* enc_w  = (const float*)d_in[1];
    const float* enc_b  = (const float*)d_in[2];
    const float* triz_w = (const float*)d_in[3];   // [40,64,64] == W[2560,64]
    const float* triz_b = (const float*)d_in[4];   // [40,64]    == bias[2560]
    const float* pol_w  = (const float*)d_in[5];
    const float* pol_b  = (const float*)d_in[6];
    const float* dec_w  = (const float*)d_in[7];
    const float* dec_b  = (const float*)d_in[8];

    int B = in_sizes[0] / 5;

    float* out   = (float*)d_out;                  // [B,5]
    float* probs = out + (size_t)B * 5;            // [B,40]
    float* h     = probs + (size_t)B * NEXP;       // [B,40,64]

    enc_kernel<<<(B * HID) / 256, 256>>>(x, enc_w, enc_b);
    wsplit_kernel<<<(NCOL * HID + 255) / 256, 256>>>(triz_w);
    policy_kernel<<<1024, 256>>>(pol_w, pol_b, probs, B);

    cudaFuncSetAttribute(gemm_h_mma,
                         cudaFuncAttributeMaxDynamicSharedMemorySize, SMEM_MMA);
    gemm_h_mma<<<B / 128, 256, SMEM_MMA>>>(triz_b, h);

    dec_kernel<<<(B + 255) / 256, 256>>>(h, dec_w, dec_b, out, B);
}

// round 17
// speedup vs baseline: 1.9060x; 1.6327x over previous
#include <cuda_runtime.h>
#include <cuda_bf16.h>
#include <cstdint>

// ---------------------------------------------------------------------------
// TRIZRL: encoder(tanh) -> 40-expert batched GEMM(+bias,relu) -> softmax router
//         -> jax.random.categorical(threefry, partitionable) -> gather -> decoder
// Outputs: out[B,5], probs[B,40], h[B,40,64]
// R17: R13 skeleton (N=128 iters, occ 2) + DE-DUP limb layout with fragment
//      reuse: each distinct A/B fragment loaded once, all 3 split terms fired
//      from registers. 48 LDMX4 / 192 MMA per warp-iter (was 72).
// ---------------------------------------------------------------------------

#define MAXB 131072
#define NEXP 40
#define HID  64
#define NCOL (NEXP * HID)   // 2560
#define KL   128            // limb-concat K (z1|z2 / w1|w2), bf16
#define SPAD 136            // smem row stride in bf16 (272B; 272%128=16 -> conflict-free)
#define ROWB 272

__device__ float         g_z [(size_t)MAXB * HID];
__device__ __nv_bfloat16 g_zc[(size_t)MAXB * KL];   // [z1 | z2]
__device__ __nv_bfloat16 g_wc[(size_t)NCOL * KL];   // [w1 | w2]
__device__ int           g_idx[MAXB];

// ---------------- Threefry-2x32-20, key (0,1); partitionable path ----------
__device__ __forceinline__ uint2 threefry01(uint32_t x0, uint32_t x1) {
    const uint32_t ks0 = 0u, ks1 = 1u, ks2 = 0x1BD11BDBu;
    x0 += ks0; x1 += ks1;
#define TFR(r) { x0 += x1; x1 = (x1 << (r)) | (x1 >> (32 - (r))); x1 ^= x0; }
    TFR(13) TFR(15) TFR(26) TFR(6)   x0 += ks1; x1 += ks2 + 1u;
    TFR(17) TFR(29) TFR(16) TFR(24)  x0 += ks2; x1 += ks0 + 2u;
    TFR(13) TFR(15) TFR(26) TFR(6)   x0 += ks0; x1 += ks1 + 3u;
    TFR(17) TFR(29) TFR(16) TFR(24)  x0 += ks1; x1 += ks2 + 4u;
    TFR(13) TFR(15) TFR(26) TFR(6)   x0 += ks2; x1 += ks0 + 5u;
#undef TFR
    return make_uint2(x0, x1);
}
__device__ __forceinline__ float gumbel_sample(uint32_t flat_idx) {
    uint2 r = threefry01(0u, flat_idx);
    uint32_t bits = r.x ^ r.y;
    float f = __uint_as_float((bits >> 9) | 0x3f800000u) - 1.0f;
    float u = fmaxf(f, 1.17549435e-38f);
    return -logf(-logf(u));
}

// ---------------- Kernel 1: encoder (+ limb emit) --------------------------
__global__ void enc_kernel(const float* __restrict__ x,
                           const float* __restrict__ ew,
                           const float* __restrict__ eb) {
    int t = blockIdx.x * blockDim.x + threadIdx.x;
    int b = t >> 6, j = t & 63;
    const float* xr = x + (size_t)b * 5;
    float a = __ldg(eb + j);
    #pragma unroll
    for (int d = 0; d < 5; ++d) a = fmaf(__ldg(xr + d), __ldg(ew + j * 5 + d), a);
    float z = tanhf(a);
    g_z[t] = z;
    __nv_bfloat16 hi = __float2bfloat16(z);
    __nv_bfloat16 lo = __float2bfloat16(z - __bfloat162float(hi));
    __nv_bfloat16* row = g_zc + (size_t)b * KL;
    row[j]      = hi;
    row[j + 64] = lo;
}

// ---------------- Kernel 1b: weight limb split -----------------------------
__global__ void wsplit_kernel(const float* __restrict__ w) {
    int i = blockIdx.x * 256 + threadIdx.x;
    if (i >= NCOL * HID) return;
    int n = i >> 6, k = i & 63;
    float v = w[i];
    __nv_bfloat16 hi = __float2bfloat16(v);
    __nv_bfloat16 lo = __float2bfloat16(v - __bfloat162float(hi));
    __nv_bfloat16* row = g_wc + (size_t)n * KL;
    row[k]      = hi;
    row[k + 64] = lo;
}

// ---------------- Kernel 2: router softmax + categorical (FROZEN) ----------
__global__ void policy_kernel(const float* __restrict__ pol_w,
                              const float* __restrict__ pol_b,
                              float* __restrict__ probs, int B) {
    __shared__ float sW[NEXP * 65];
    __shared__ float sB[NEXP];
    __shared__ float sZ[8][HID];
    int tid = threadIdx.x;
    for (int i = tid; i < NEXP * HID; i += 256)
        sW[(i / HID) * 65 + (i % HID)] = pol_w[i];
    if (tid < NEXP) sB[tid] = pol_b[tid];
    __syncthreads();

    int wid = tid >> 5, lane = tid & 31;
    int gw = blockIdx.x * 8 + wid;
    int warpsTotal = gridDim.x * 8;

    for (int b = gw; b < B; b += warpsTotal) {
        const float* zr = g_z + (size_t)b * HID;
        sZ[wid][lane]      = zr[lane];
        sZ[wid][lane + 32] = zr[lane + 32];
        __syncwarp();

        float acc1 = 0.f, acc2 = 0.f;
        #pragma unroll
        for (int d = 0; d < HID; ++d) {
            float zd = sZ[wid][d];
            acc1 = fmaf(zd, sW[lane * 65 + d], acc1);
            if (lane < 8) acc2 = fmaf(zd, sW[(lane + 32) * 65 + d], acc2);
        }
        float v1 = acc1 + sB[lane];
        float v2 = (lane < 8) ? (acc2 + sB[lane + 32]) : -INFINITY;

        float m = fmaxf(v1, v2);
        #pragma unroll
        for (int off = 16; off; off >>= 1) m = fmaxf(m, __shfl_xor_sync(~0u, m, off));
        float e1 = expf(v1 - m);
        float e2 = (lane < 8) ? expf(v2 - m) : 0.f;
        float s = e1 + e2;
        #pragma unroll
        for (int off = 16; off; off >>= 1) s += __shfl_xor_sync(~0u, s, off);
        float p1 = e1 / s, p2 = e2 / s;
        probs[(size_t)b * NEXP + lane] = p1;
        if (lane < 8) probs[(size_t)b * NEXP + 32 + lane] = p2;

        uint32_t base = (uint32_t)b * (uint32_t)NEXP;
        float val1 = logf(p1) + gumbel_sample(base + lane);
        float val2 = -INFINITY;
        if (lane < 8) val2 = logf(p2) + gumbel_sample(base + 32 + lane);

        float bv; int bk;
        if (val2 > val1) { bv = val2; bk = lane + 32; } else { bv = val1; bk = lane; }
        #pragma unroll
        for (int off = 16; off; off >>= 1) {
            float ov = __shfl_xor_sync(~0u, bv, off);
            int   ok = __shfl_xor_sync(~0u, bk, off);
            if (ov > bv || (ov == bv && ok < bk)) { bv = ov; bk = ok; }
        }
        if (lane == 0) g_idx[b] = bk;
        __syncwarp();
    }
}

// ---------------- Kernel 3: h-GEMM, dedup limbs + frag reuse ---------------
__device__ __forceinline__ uint32_t smem_u32(const void* p) {
    uint32_t a;
    asm("{ .reg .u64 t; cvta.to.shared.u64 t, %1; cvt.u32.u64 %0, t; }" : "=r"(a) : "l"(p));
    return a;
}
#define LDMX4(r0, r1, r2, r3, addr) \
    asm volatile("ldmatrix.sync.aligned.m8n8.x4.shared.b16 {%0,%1,%2,%3}, [%4];" \
        : "=r"(r0), "=r"(r1), "=r"(r2), "=r"(r3) : "r"(addr))
#define BMMA(acc, a, b) \
    asm volatile( \
        "mma.sync.aligned.m16n8k16.row.col.f32.bf16.bf16.f32 " \
        "{%0,%1,%2,%3}, {%4,%5,%6,%7}, {%8,%9}, {%0,%1,%2,%3};" \
        : "+f"((acc)[0]), "+f"((acc)[1]), "+f"((acc)[2]), "+f"((acc)[3]) \
        : "r"((a)[0]), "r"((a)[1]), "r"((a)[2]), "r"((a)[3]), \
          "r"((b)[0]), "r"((b)[1]))

// 4x4 transpose of float2 elements within a quad (2 shfl_xor stages).
__device__ __forceinline__ void quad_tr4(unsigned long long* P, int lc) {
    {
        bool hi = lc & 2;
        unsigned long long s0 = hi ? P[0] : P[2];
        unsigned long long s1 = hi ? P[1] : P[3];
        unsigned long long r0 = __shfl_xor_sync(0xffffffffu, s0, 2);
        unsigned long long r1 = __shfl_xor_sync(0xffffffffu, s1, 2);
        if (hi) { P[0] = r0; P[1] = r1; } else { P[2] = r0; P[3] = r1; }
    }
    {
        bool od = lc & 1;
        unsigned long long s0 = od ? P[0] : P[1];
        unsigned long long s1 = od ? P[2] : P[3];
        unsigned long long r0 = __shfl_xor_sync(0xffffffffu, s0, 1);
        unsigned long long r1 = __shfl_xor_sync(0xffffffffu, s1, 1);
        if (od) { P[0] = r0; P[2] = r1; } else { P[1] = r0; P[3] = r1; }
    }
}
__device__ __forceinline__ unsigned long long pack2(float x, float y) {
    unsigned long long r;
    asm("mov.b64 %0, {%1, %2};" : "=l"(r) : "f"(x), "f"(y));
    return r;
}
__device__ __forceinline__ float2 unpack2(unsigned long long v) {
    float2 r;
    asm("mov.b64 {%0, %1}, %2;" : "=f"(r.x), "=f"(r.y) : "l"(v));
    return r;
}

// CTA: M=128 rows resident (A smem 128x272B = [z1|z2]). 20 iters of N=128.
// 8 warps 4m x 2n, warp tile m32 x n64, acc[2][8][4].
// Per sub-step s: load a1,a2 (4 LDMX4); per n-half: b1,b2 (4 LDMX4) -> 24 MMA:
//   acc += a1*b1 + a1*b2 + a2*b1   (z1w1 + z1w2 + z2w1)
__global__ void __launch_bounds__(256, 2)
gemm_h_mma(const float* __restrict__ bias, float* __restrict__ H) {
    extern __shared__ __nv_bfloat16 sm[];
    __nv_bfloat16* As = sm;               // [128][SPAD]
    __nv_bfloat16* Bs = sm + 128 * SPAD;  // [128][SPAD]

    int tid = threadIdx.x;
    size_t bm = (size_t)blockIdx.x * 128;

    // A tile: 128 rows x 256B = 2048 x 16B chunks
    #pragma unroll
    for (int it = 0; it < 8; ++it) {
        int i = tid + it * 256;
        int m = i >> 4, c = i & 15;
        uint4 v = *(const uint4*)(g_zc + (bm + m) * KL + c * 8);
        *(uint4*)(As + m * SPAD + c * 8) = v;
    }

    int wid = tid >> 5, lane = tid & 31;
    int mw = (wid & 3) * 32;        // warp m offset
    int nw = (wid >> 2) * 64;       // warp n offset (n64 per warp)
    int lr = lane >> 2, lc = lane & 3;

    uint32_t sbA = smem_u32(As), sbB = smem_u32(Bs);
    uint32_t aoff = sbA + (((lane & 7) + ((lane >> 3) & 1) * 8) * ROWB
                           + ((lane >> 4) & 1) * 16);
    uint32_t boff = sbB + nw * ROWB + (((lane & 7) + ((lane >> 4) & 1) * 8) * ROWB
                           + ((lane >> 3) & 1) * 16);

    for (int t = 0; t < NEXP / 2; ++t) {
        int bn = t * 128;
        __syncthreads();                   // prev Bs consumed
        // B tile: 128 rows x 256B = 2048 chunks
        #pragma unroll
        for (int it = 0; it < 8; ++it) {
            int i = tid + it * 256;
            int n = i >> 4, c = i & 15;
            uint4 v = *(const uint4*)(g_wc + (size_t)(bn + n) * KL + c * 8);
            *(uint4*)(Bs + n * SPAD + c * 8) = v;
        }
        __syncthreads();                   // Bs ready

        float acc[2][8][4];
        #pragma unroll
        for (int f = 0; f < 2; ++f)
            #pragma unroll
            for (int g = 0; g < 8; ++g)
                #pragma unroll
                for (int e = 0; e < 4; ++e) acc[f][g][e] = 0.f;

        #pragma unroll
        for (int s = 0; s < 4; ++s) {
            uint32_t a1[2][4], a2[2][4];
            #pragma unroll
            for (int f = 0; f < 2; ++f) {
                LDMX4(a1[f][0], a1[f][1], a1[f][2], a1[f][3],
                      aoff + (mw + f * 16) * ROWB + s * 32);          // z1
                LDMX4(a2[f][0], a2[f][1], a2[f][2], a2[f][3],
                      aoff + (mw + f * 16) * ROWB + 128 + s * 32);    // z2
            }
            #pragma unroll
            for (int gh = 0; gh < 2; ++gh) {
                uint32_t b1[4][2], b2[4][2];
                uint32_t bb = boff + (gh * 32) * ROWB + s * 32;
                LDMX4(b1[0][0], b1[0][1], b1[1][0], b1[1][1], bb);              // w1
                LDMX4(b1[2][0], b1[2][1], b1[3][0], b1[3][1], bb + 16 * ROWB);
                LDMX4(b2[0][0], b2[0][1], b2[1][0], b2[1][1], bb + 128);        // w2
                LDMX4(b2[2][0], b2[2][1], b2[3][0], b2[3][1], bb + 128 + 16 * ROWB);
                #pragma unroll
                for (int f = 0; f < 2; ++f)
                    #pragma unroll
                    for (int g4 = 0; g4 < 4; ++g4) {
                        int gg = gh * 4 + g4;
                        BMMA(acc[f][gg], a1[f], b1[g4]);   // z1*w1
                        BMMA(acc[f][gg], a1[f], b2[g4]);   // z1*w2
                        BMMA(acc[f][gg], a2[f], b1[g4]);   // z2*w1
                    }
            }
        }

        // Epilogue: bias+relu, quad transpose, STG.128 (R13 verbatim).
        #pragma unroll
        for (int f = 0; f < 2; ++f) {
            #pragma unroll
            for (int nh = 0; nh < 2; ++nh) {
                unsigned long long P[4], Q[4];
                #pragma unroll
                for (int g = 0; g < 4; ++g) {
                    int gg = nh * 4 + g;
                    int col = bn + nw + nh * 32 + g * 8 + lc * 2;
                    float b0 = __ldg(bias + col), b1 = __ldg(bias + col + 1);
                    P[g] = pack2(fmaxf(acc[f][gg][0] + b0, 0.f),
                                 fmaxf(acc[f][gg][1] + b1, 0.f));
                    Q[g] = pack2(fmaxf(acc[f][gg][2] + b0, 0.f),
                                 fmaxf(acc[f][gg][3] + b1, 0.f));
                }
                quad_tr4(P, lc);
                quad_tr4(Q, lc);
                size_t r0 = bm + mw + f * 16 + lr;
                float* o0 = H + r0 * NCOL + bn + nw + nh * 32 + lc * 8;
                float* o1 = o0 + (size_t)8 * NCOL;
                float2 p0 = unpack2(P[0]), p1 = unpack2(P[1]);
                float2 p2 = unpack2(P[2]), p3 = unpack2(P[3]);
                float2 q0 = unpack2(Q[0]), q1 = unpack2(Q[1]);
                float2 q2 = unpack2(Q[2]), q3 = unpack2(Q[3]);
                *(float4*)(o0)     = make_float4(p0.x, p0.y, p1.x, p1.y);
                *(float4*)(o0 + 4) = make_float4(p2.x, p2.y, p3.x, p3.y);
                *(float4*)(o1)     = make_float4(q0.x, q0.y, q1.x, q1.y);
                *(float4*)(o1 + 4) = make_float4(q2.x, q2.y, q3.x, q3.y);
            }
        }
    }
}

// ---------------- Kernel 4: decoder ----------------------------------------
__global__ void dec_kernel(const float* __restrict__ H,
                           const float* __restrict__ dw,
                           const float* __restrict__ db,
                           float* __restrict__ out, int B) {
    __shared__ float sw[5 * HID];
    __shared__ float sb[5];
    int tid = threadIdx.x;
    for (int i = tid; i < 5 * HID; i += 256) sw[i] = dw[i];
    if (tid < 5) sb[tid] = db[tid];
    __syncthreads();

    int b = blockIdx.x * 256 + tid;
    if (b >= B) return;
    const float4* hr = (const float4*)(H + (size_t)b * NCOL + g_idx[b] * HID);
    float acc[5];
    #pragma unroll
    for (int j = 0; j < 5; ++j) acc[j] = sb[j];
    #pragma unroll
    for (int q = 0; q < 16; ++q) {
        float4 v = hr[q];
        #pragma unroll
        for (int j = 0; j < 5; ++j) {
            acc[j] = fmaf(v.x, sw[j * HID + q * 4 + 0], acc[j]);
            acc[j] = fmaf(v.y, sw[j * HID + q * 4 + 1], acc[j]);
            acc[j] = fmaf(v.z, sw[j * HID + q * 4 + 2], acc[j]);
            acc[j] = fmaf(v.w, sw[j * HID + q * 4 + 3], acc[j]);
        }
    }
    float* o = out + (size_t)b * 5;
    #pragma unroll
    for (int j = 0; j < 5; ++j) o[j] = acc[j];
}

// ---------------------------------------------------------------------------
#define SMEM_MMA ((128 * SPAD + 128 * SPAD) * 2)   // 69632 bytes

extern "C" void kernel_launch(void* const* d_in, const int* in_sizes, int n_in,
                              void* d_out, int out_size) {
    const float* x      = (const float*)d_in[0];
    const float* enc_w  = (const float*)d_in[1];
    const float* enc_b  = (const float*)d_in[2];
    const float* triz_w = (const float*)d_in[3];   // [40,64,64] == W[2560,64]
    const float* triz_b = (const float*)d_in[4];   // [40,64]    == bias[2560]
    const float* pol_w  = (const float*)d_in[5];
    const float* pol_b  = (const float*)d_in[6];
    const float* dec_w  = (const float*)d_in[7];
    const float* dec_b  = (const float*)d_in[8];

    int B = in_sizes[0] / 5;

    float* out   = (float*)d_out;                  // [B,5]
    float* probs = out + (size_t)B * 5;            // [B,40]
    float* h     = probs + (size_t)B * NEXP;       // [B,40,64]

    enc_kernel<<<(B * HID) / 256, 256>>>(x, enc_w, enc_b);
    wsplit_kernel<<<(NCOL * HID + 255) / 256, 256>>>(triz_w);
    policy_kernel<<<1024, 256>>>(pol_w, pol_b, probs, B);

    cudaFuncSetAttribute(gemm_h_mma,
                         cudaFuncAttributeMaxDynamicSharedMemorySize, SMEM_MMA);
    gemm_h_mma<<<B / 128, 256, SMEM_MMA>>>(triz_b, h);

    dec_kernel<<<(B + 255) / 256, 256>>>(h, dec_w, dec_b, out, B);
}